// round 1
// baseline (speedup 1.0000x reference)
#include <cuda_runtime.h>

// BYOL loss: out = 2 - 2 * mean_i( dot(x_i, xt_i) / (max(||x_i||,eps)*max(||xt_i||,eps)) )
// Only the diagonal of the cosine-sim matrix is needed -> O(N*D) streaming.

#define N_ROWS 8192
#define D_DIM  512
#define EPS 1e-8f

__device__ float g_row_cos[N_ROWS];

// One block (128 threads) per row. D=512 floats = 128 float4 -> 1 float4/thread/input.
__global__ void __launch_bounds__(128) row_cos_kernel(
    const float* __restrict__ x, const float* __restrict__ xt)
{
    const int row = blockIdx.x;
    const int t = threadIdx.x;

    const float4* a4 = reinterpret_cast<const float4*>(x  + (size_t)row * D_DIM);
    const float4* b4 = reinterpret_cast<const float4*>(xt + (size_t)row * D_DIM);

    float4 av = a4[t];
    float4 bv = b4[t];

    float dot = av.x*bv.x + av.y*bv.y + av.z*bv.z + av.w*bv.w;
    float aa  = av.x*av.x + av.y*av.y + av.z*av.z + av.w*av.w;
    float bb  = bv.x*bv.x + bv.y*bv.y + bv.z*bv.z + bv.w*bv.w;

    // warp reduction (3 values)
    #pragma unroll
    for (int off = 16; off > 0; off >>= 1) {
        dot += __shfl_xor_sync(0xFFFFFFFFu, dot, off);
        aa  += __shfl_xor_sync(0xFFFFFFFFu, aa,  off);
        bb  += __shfl_xor_sync(0xFFFFFFFFu, bb,  off);
    }

    __shared__ float sd[4], sa[4], sb[4];
    const int w = t >> 5;
    const int l = t & 31;
    if (l == 0) { sd[w] = dot; sa[w] = aa; sb[w] = bb; }
    __syncthreads();

    if (t == 0) {
        float Dd = sd[0] + sd[1] + sd[2] + sd[3];
        float Aa = sa[0] + sa[1] + sa[2] + sa[3];
        float Bb = sb[0] + sb[1] + sb[2] + sb[3];
        float na = fmaxf(sqrtf(Aa), EPS);
        float nb = fmaxf(sqrtf(Bb), EPS);
        g_row_cos[row] = Dd / (na * nb);
    }
}

// Single-block deterministic reduction over 8192 row cosines.
__global__ void __launch_bounds__(1024) reduce_kernel(float* __restrict__ out)
{
    const int t = threadIdx.x;
    float s = 0.0f;
    #pragma unroll
    for (int i = t; i < N_ROWS; i += 1024) s += g_row_cos[i];

    // warp reduce
    #pragma unroll
    for (int off = 16; off > 0; off >>= 1)
        s += __shfl_xor_sync(0xFFFFFFFFu, s, off);

    __shared__ float sw[32];
    const int w = t >> 5, l = t & 31;
    if (l == 0) sw[w] = s;
    __syncthreads();

    if (w == 0) {
        float v = (l < 32) ? sw[l] : 0.0f;  // 1024 threads -> 32 warps
        #pragma unroll
        for (int off = 16; off > 0; off >>= 1)
            v += __shfl_xor_sync(0xFFFFFFFFu, v, off);
        if (l == 0)
            out[0] = 2.0f - 2.0f * (v / (float)N_ROWS);
    }
}

extern "C" void kernel_launch(void* const* d_in, const int* in_sizes, int n_in,
                              void* d_out, int out_size)
{
    const float* x  = (const float*)d_in[0];
    const float* xt = (const float*)d_in[1];
    float* out = (float*)d_out;

    row_cos_kernel<<<N_ROWS, 128>>>(x, xt);
    reduce_kernel<<<1, 1024>>>(out);
}

// round 3
// speedup vs baseline: 1.1621x; 1.1621x over previous
#include <cuda_runtime.h>

// BYOL loss: out = 2 - 2 * mean_i( dot(x_i, xt_i) / (max(||x_i||,eps)*max(||xt_i||,eps)) )
// Fused single kernel: per-row cosine (1 warp/row) + last-block-retires global reduce.

#define N_ROWS 8192
#define D_DIM  512
#define EPS 1e-8f

#define NBLOCKS 1024
#define NTHREADS 256   // 8 warps -> 8 rows per block

__device__ float g_partial[NBLOCKS];
__device__ unsigned int g_count = 0;

__global__ void __launch_bounds__(NTHREADS) byol_fused_kernel(
    const float* __restrict__ x, const float* __restrict__ xt,
    float* __restrict__ out)
{
    const int t = threadIdx.x;
    const int lane = t & 31;
    const int warp = t >> 5;                 // 0..7
    const int row = blockIdx.x * 8 + warp;   // 1024*8 = 8192 rows

    // ---- per-row cosine (one warp per row) ----
    const float4* a4 = reinterpret_cast<const float4*>(x  + (size_t)row * D_DIM);
    const float4* b4 = reinterpret_cast<const float4*>(xt + (size_t)row * D_DIM);

    float4 av[4], bv[4];
    #pragma unroll
    for (int i = 0; i < 4; i++) av[i] = a4[lane + 32 * i];
    #pragma unroll
    for (int i = 0; i < 4; i++) bv[i] = b4[lane + 32 * i];

    float dot = 0.f, aa = 0.f, bb = 0.f;
    #pragma unroll
    for (int i = 0; i < 4; i++) {
        dot += av[i].x*bv[i].x + av[i].y*bv[i].y + av[i].z*bv[i].z + av[i].w*bv[i].w;
        aa  += av[i].x*av[i].x + av[i].y*av[i].y + av[i].z*av[i].z + av[i].w*av[i].w;
        bb  += bv[i].x*bv[i].x + bv[i].y*bv[i].y + bv[i].z*bv[i].z + bv[i].w*bv[i].w;
    }

    #pragma unroll
    for (int off = 16; off > 0; off >>= 1) {
        dot += __shfl_xor_sync(0xFFFFFFFFu, dot, off);
        aa  += __shfl_xor_sync(0xFFFFFFFFu, aa,  off);
        bb  += __shfl_xor_sync(0xFFFFFFFFu, bb,  off);
    }

    __shared__ float s_cos[8];
    if (lane == 0) {
        float na = fmaxf(sqrtf(aa), EPS);
        float nb = fmaxf(sqrtf(bb), EPS);
        s_cos[warp] = dot / (na * nb);
    }
    __syncthreads();

    // ---- block partial + retirement ----
    __shared__ bool s_last;
    if (t == 0) {
        float p = s_cos[0] + s_cos[1] + s_cos[2] + s_cos[3]
                + s_cos[4] + s_cos[5] + s_cos[6] + s_cos[7];
        g_partial[blockIdx.x] = p;
        __threadfence();
        // wraps to 0 when old == NBLOCKS-1 -> counter self-resets for graph replay
        unsigned int old = atomicInc(&g_count, NBLOCKS - 1);
        s_last = (old == NBLOCKS - 1);
    }
    __syncthreads();

    if (!s_last) return;

    // ---- last block: deterministic reduce of 1024 partials ----
    float s = 0.f;
    #pragma unroll
    for (int i = 0; i < NBLOCKS / NTHREADS; i++)   // fixed order per thread
        s += g_partial[t + NTHREADS * i];

    #pragma unroll
    for (int off = 16; off > 0; off >>= 1)
        s += __shfl_xor_sync(0xFFFFFFFFu, s, off);

    __shared__ float s_w[8];
    if (lane == 0) s_w[warp] = s;
    __syncthreads();

    if (t == 0) {
        float v = s_w[0] + s_w[1] + s_w[2] + s_w[3]
                + s_w[4] + s_w[5] + s_w[6] + s_w[7];
        out[0] = 2.0f - 2.0f * (v / (float)N_ROWS);
    }
}

extern "C" void kernel_launch(void* const* d_in, const int* in_sizes, int n_in,
                              void* d_out, int out_size)
{
    const float* x  = (const float*)d_in[0];
    const float* xt = (const float*)d_in[1];
    float* out = (float*)d_out;

    byol_fused_kernel<<<NBLOCKS, NTHREADS>>>(x, xt, out);
}